// round 2
// baseline (speedup 1.0000x reference)
#include <cuda_runtime.h>
#include <math.h>

#define H 256
#define N_STATE 64
#define L 2048
#define BATCH 8

#define OT 512          // output tile (time) per block
#define MT 256          // input tile (time)
#define NTHREADS 64     // each thread owns 8 consecutive lags x 2 batches
#define KSZ (OT + MT + 32)

typedef unsigned long long ull;

// scratch (no allocation allowed)
__device__ float4 g_params[H * N_STATE];   // {Ceff_r, Ceff_i, dtA_r, dtA_i}
__device__ float  g_k[H * L];              // SSM convolution kernel
__device__ int    g_lcut[H];               // per-head kernel cutoff

#define FMA2(acc, a, b) asm("fma.rn.f32x2 %0, %1, %2, %0;" : "+l"(acc) : "l"(a), "l"(b))

// ---------------------------------------------------------------------------
// Kernel 1: per-(h,n) parameters, replicating the reference's fp32 op order.
// ---------------------------------------------------------------------------
__global__ void s4d_params_kernel(const float* __restrict__ A_real,
                                  const float* __restrict__ A_imag,
                                  const float* __restrict__ Bm,
                                  const float* __restrict__ Cm,
                                  const float* __restrict__ inv_dt)
{
    int idx = blockIdx.x * blockDim.x + threadIdx.x;
    if (idx >= H * N_STATE) return;
    int h = idx / N_STATE;

    float Ar = -expf(A_real[idx]);          // A = -exp(A_real) - i*A_imag
    float Ai = -A_imag[idx];
    float dt = (float)exp((double)inv_dt[h]);
    float dtAr = dt * Ar;
    float dtAi = dt * Ai;

    float er = expf(dtAr);
    double sd, cd;
    sincos((double)dtAi, &sd, &cd);
    float Er = fmaf(er, (float)cd, -1.0f);
    float Ei = er * (float)sd;

    float br = Bm[2 * idx], bi = Bm[2 * idx + 1];
    float cr = Cm[2 * idx], ci = Cm[2 * idx + 1];
    float bcr = br * cr - bi * ci;
    float bci = br * ci + bi * cr;
    float tr = bcr * Er - bci * Ei;
    float ti = bcr * Ei + bci * Er;
    float inv = 1.0f / (Ar * Ar + Ai * Ai);
    float cer = (tr * Ar + ti * Ai) * inv;
    float cei = (ti * Ar - tr * Ai) * inv;

    g_params[idx] = make_float4(cer, cei, dtAr, dtAi);

    // per-head truncation point: decay e^{dtAr*l}; cut at e^-16 (~1.1e-7)
    if ((idx & (N_STATE - 1)) == 0) {
        float rate = -dtAr;                 // > 0
        int lc = (int)(16.0f / rate) + 1;
        g_lcut[h] = lc < L ? lc : L;
    }
}

// ---------------------------------------------------------------------------
// Kernel 2: k[h,l] = 2 * sum_n Re(Ceff * exp(dtA_r*l) * cis(fl32(dtA_i*l)))
// ---------------------------------------------------------------------------
__global__ void s4d_kgen_kernel(void)
{
    __shared__ float4 sp[N_STATE];
    int h = blockIdx.y;
    int l = blockIdx.x * blockDim.x + threadIdx.x;
    if (threadIdx.x < N_STATE) sp[threadIdx.x] = g_params[h * N_STATE + threadIdx.x];
    __syncthreads();

    const double INV2PI = 0.15915494309189535;
    const double TWOPI  = 6.283185307179586;
    const float  TWO_OVER_PI = 0.6366197723675814f;
    const float  PIO2_HI = 1.57079637050628662109375f;
    const float  PIO2_LO = -4.37113900018624283e-8f;

    float fl = (float)l;
    float acc = 0.0f;

    #pragma unroll 4
    for (int n = 0; n < N_STATE; n++) {
        float4 p = sp[n];
        float theta = p.w * fl;                 // fp32 product — matches reference
        float decay = expf(p.z * fl);

        double td = (double)theta;
        double qd = rint(td * INV2PI);
        float r = (float)fma(-qd, TWOPI, td);

        float qf = rintf(r * TWO_OVER_PI);
        float rr = fmaf(-qf, PIO2_HI, r);
        rr = fmaf(-qf, PIO2_LO, rr);
        int qi = (int)qf & 3;

        float x2 = rr * rr;
        float s = fmaf(x2, 2.75573192e-6f, -1.98412698e-4f);
        s = fmaf(x2, s, 8.33333333e-3f);
        s = fmaf(x2, s, -1.66666667e-1f);
        s = rr * fmaf(x2, s, 1.0f);
        float c = fmaf(x2, 2.48015873e-5f, -1.38888889e-3f);
        c = fmaf(x2, c, 4.16666667e-2f);
        c = fmaf(x2, c, -0.5f);
        c = fmaf(x2, c, 1.0f);

        float S, C;
        switch (qi) {
            case 0: S = s;  C = c;  break;
            case 1: S = c;  C = -s; break;
            case 2: S = -s; C = -c; break;
            default: S = -c; C = s; break;
        }
        acc = fmaf(decay, fmaf(p.x, C, -p.y * S), acc);
    }
    g_k[h * L + l] = 2.0f * acc;
}

// ---------------------------------------------------------------------------
// Kernel 3: causal conv over a BATCH PAIR using packed f32x2 FMA.
// Block = (t-tile, h, batch-pair). Each thread owns 8 consecutive lags;
// each f32x2 accumulator holds (y_b0, y_b1) for one lag.
// k is stored REVERSED and DUPLICATED (k,k) in smem so the per-thread window
// slides with m and loads are conflict-light LDS.64; x pairs are broadcasts.
// ---------------------------------------------------------------------------
__global__ void __launch_bounds__(NTHREADS)
s4d_conv_kernel(const float* __restrict__ x, float* __restrict__ y)
{
    __shared__ __align__(16) float2 xs2[MT];
    __shared__ __align__(16) ull   kshd[KSZ];

    int t0 = blockIdx.x * OT;
    int h  = blockIdx.y;
    int b0 = blockIdx.z * 2;
    int tid = threadIdx.x;

    const float* xrow0 = x + (b0 * H + h) * L;
    const float* xrow1 = x + ((b0 + 1) * H + h) * L;
    const float* krow  = g_k + h * L;
    int lcut = g_lcut[h];

    ull acc[8];
    #pragma unroll
    for (int j = 0; j < 8; j++) acc[j] = 0ull;

    int ms = t0 - lcut;
    int m0_start = ms > 0 ? (ms / MT) * MT : 0;
    int ib0 = OT - 8 - 8 * tid;          // window base in kshd (element units)

    for (int m0 = m0_start; m0 <= t0 + OT - MT; m0 += MT) {
        __syncthreads();
        #pragma unroll
        for (int i = tid; i < MT; i += NTHREADS)
            xs2[i] = make_float2(xrow0[m0 + i], xrow1[m0 + i]);
        int qmax = t0 + OT - 1 - m0;
        #pragma unroll
        for (int i = tid; i < KSZ; i += NTHREADS) {
            int q = qmax - i;
            float kv = (q >= 0) ? krow[q] : 0.0f;   // q <= 2047 always
            unsigned int u = __float_as_uint(kv);
            kshd[i] = ((ull)u << 32) | u;
        }
        __syncthreads();

        const ull* kd = kshd + ib0;
        ull kpA[8], kpB[8];
        #pragma unroll
        for (int j = 0; j < 8; j++) kpA[j] = kd[j];

        #pragma unroll 1
        for (int m = 0; m < MT; m += 16) {
            #pragma unroll
            for (int j = 0; j < 8; j++) kpB[j] = kd[m + 8 + j];
            #pragma unroll
            for (int s = 0; s < 8; s++) {
                ull xp = *reinterpret_cast<const ull*>(&xs2[m + s]);
                #pragma unroll
                for (int j = 7; j >= 0; j--) {
                    int idx = s + 7 - j;
                    if (idx < 8) FMA2(acc[j], kpA[idx], xp);
                    else         FMA2(acc[j], kpB[idx - 8], xp);
                }
            }
            #pragma unroll
            for (int j = 0; j < 8; j++) kpA[j] = kd[m + 16 + j];
            #pragma unroll
            for (int s = 0; s < 8; s++) {
                ull xp = *reinterpret_cast<const ull*>(&xs2[m + 8 + s]);
                #pragma unroll
                for (int j = 7; j >= 0; j--) {
                    int idx = s + 7 - j;
                    if (idx < 8) FMA2(acc[j], kpB[idx], xp);
                    else         FMA2(acc[j], kpA[idx - 8], xp);
                }
            }
        }
    }

    // epilogue: unpack (b0,b1), ReLU, vectorized stores
    float r0[8], r1[8];
    #pragma unroll
    for (int j = 0; j < 8; j++) {
        float v0 = __uint_as_float((unsigned int)(acc[j] & 0xffffffffull));
        float v1 = __uint_as_float((unsigned int)(acc[j] >> 32));
        r0[j] = v0 > 0.0f ? v0 : 0.0f;
        r1[j] = v1 > 0.0f ? v1 : 0.0f;
    }
    float* yr0 = y + (b0 * H + h) * L + t0 + 8 * tid;
    float* yr1 = y + ((b0 + 1) * H + h) * L + t0 + 8 * tid;
    *(float4*)(yr0)     = make_float4(r0[0], r0[1], r0[2], r0[3]);
    *(float4*)(yr0 + 4) = make_float4(r0[4], r0[5], r0[6], r0[7]);
    *(float4*)(yr1)     = make_float4(r1[0], r1[1], r1[2], r1[3]);
    *(float4*)(yr1 + 4) = make_float4(r1[4], r1[5], r1[6], r1[7]);
}

// ---------------------------------------------------------------------------
extern "C" void kernel_launch(void* const* d_in, const int* in_sizes, int n_in,
                              void* d_out, int out_size)
{
    const float* x      = (const float*)d_in[0];   // (B, H, L)
    const float* A_real = (const float*)d_in[1];   // (H, N)
    const float* A_imag = (const float*)d_in[2];   // (H, N)
    const float* Bm     = (const float*)d_in[3];   // (1, H, N, 2)
    const float* Cm     = (const float*)d_in[4];   // (1, H, N, 2)
    const float* inv_dt = (const float*)d_in[5];   // (H, 1)
    float* y = (float*)d_out;                      // (B, 1, H, L)

    s4d_params_kernel<<<(H * N_STATE + 255) / 256, 256>>>(A_real, A_imag, Bm, Cm, inv_dt);
    s4d_kgen_kernel<<<dim3(L / 256, H), 256>>>();
    s4d_conv_kernel<<<dim3(L / OT, H, BATCH / 2), NTHREADS>>>(x, y);
}

// round 3
// speedup vs baseline: 1.2680x; 1.2680x over previous
#include <cuda_runtime.h>
#include <math.h>

#define H 256
#define N_STATE 64
#define L 2048
#define BATCH 8

#define OT 512          // output tile (time) per block
#define MT 512          // input tile (time)
#define NTHREADS 64     // each thread owns 8 consecutive outputs
#define KTOT 1032       // k values per tile (q range)
#define KSM_SZ 1168     // skewed storage: max a(i)=1031+128=1159, padded

// scratch (no allocation allowed)
__device__ float4 g_params[H * N_STATE];   // {Ceff_r, Ceff_i, dtA_r, dtA_i}
__device__ float  g_k[H * L];              // SSM convolution kernel
__device__ int    g_lcut[H];               // per-head kernel cutoff

// ---------------------------------------------------------------------------
// Kernel 1: per-(h,n) parameters, replicating the reference's fp32 op order.
// ---------------------------------------------------------------------------
__global__ void s4d_params_kernel(const float* __restrict__ A_real,
                                  const float* __restrict__ A_imag,
                                  const float* __restrict__ Bm,
                                  const float* __restrict__ Cm,
                                  const float* __restrict__ inv_dt)
{
    int idx = blockIdx.x * blockDim.x + threadIdx.x;
    if (idx >= H * N_STATE) return;
    int h = idx / N_STATE;

    float Ar = -expf(A_real[idx]);          // A = -exp(A_real) - i*A_imag
    float Ai = -A_imag[idx];
    float dt = (float)exp((double)inv_dt[h]);
    float dtAr = dt * Ar;
    float dtAi = dt * Ai;

    float er = expf(dtAr);
    double sd, cd;
    sincos((double)dtAi, &sd, &cd);
    float Er = fmaf(er, (float)cd, -1.0f);
    float Ei = er * (float)sd;

    float br = Bm[2 * idx], bi = Bm[2 * idx + 1];
    float cr = Cm[2 * idx], ci = Cm[2 * idx + 1];
    float bcr = br * cr - bi * ci;
    float bci = br * ci + bi * cr;
    float tr = bcr * Er - bci * Ei;
    float ti = bcr * Ei + bci * Er;
    float inv = 1.0f / (Ar * Ar + Ai * Ai);
    float cer = (tr * Ar + ti * Ai) * inv;
    float cei = (ti * Ar - tr * Ai) * inv;

    g_params[idx] = make_float4(cer, cei, dtAr, dtAi);

    // per-head truncation point: decay e^{dtAr*l}; cut at e^-16 (~1.1e-7)
    if ((idx & (N_STATE - 1)) == 0) {
        float rate = -dtAr;                 // > 0
        int lc = (int)(16.0f / rate) + 1;
        g_lcut[h] = lc < L ? lc : L;
    }
}

// ---------------------------------------------------------------------------
// Kernel 2: k[h,l] = 2 * sum_n Re(Ceff * exp(dtA_r*l) * cis(fl32(dtA_i*l)))
// ---------------------------------------------------------------------------
__global__ void s4d_kgen_kernel(void)
{
    __shared__ float4 sp[N_STATE];
    int h = blockIdx.y;
    int l = blockIdx.x * blockDim.x + threadIdx.x;
    if (threadIdx.x < N_STATE) sp[threadIdx.x] = g_params[h * N_STATE + threadIdx.x];
    __syncthreads();

    const double INV2PI = 0.15915494309189535;
    const double TWOPI  = 6.283185307179586;
    const float  TWO_OVER_PI = 0.6366197723675814f;
    const float  PIO2_HI = 1.57079637050628662109375f;
    const float  PIO2_LO = -4.37113900018624283e-8f;

    float fl = (float)l;
    float acc = 0.0f;

    #pragma unroll 4
    for (int n = 0; n < N_STATE; n++) {
        float4 p = sp[n];
        float theta = p.w * fl;                 // fp32 product — matches reference
        float decay = expf(p.z * fl);

        double td = (double)theta;
        double qd = rint(td * INV2PI);
        float r = (float)fma(-qd, TWOPI, td);

        float qf = rintf(r * TWO_OVER_PI);
        float rr = fmaf(-qf, PIO2_HI, r);
        rr = fmaf(-qf, PIO2_LO, rr);
        int qi = (int)qf & 3;

        float x2 = rr * rr;
        float s = fmaf(x2, 2.75573192e-6f, -1.98412698e-4f);
        s = fmaf(x2, s, 8.33333333e-3f);
        s = fmaf(x2, s, -1.66666667e-1f);
        s = rr * fmaf(x2, s, 1.0f);
        float c = fmaf(x2, 2.48015873e-5f, -1.38888889e-3f);
        c = fmaf(x2, c, 4.16666667e-2f);
        c = fmaf(x2, c, -0.5f);
        c = fmaf(x2, c, 1.0f);

        float S, C;
        switch (qi) {
            case 0: S = s;  C = c;  break;
            case 1: S = c;  C = -s; break;
            case 2: S = -s; C = -c; break;
            default: S = -c; C = s; break;
        }
        acc = fmaf(decay, fmaf(p.x, C, -p.y * S), acc);
    }
    g_k[h * L + l] = 2.0f * acc;
}

// ---------------------------------------------------------------------------
// Kernel 3: causal conv y[b,h,l] = sum_{m<=l} k[l-m]*x[m], then ReLU.
// 64 threads; thread owns 8 consecutive outputs l = t0+8*tid+j.
// Iterate m ascending. k held in a 16-register circular window indexed
// statically ((u-j)&15 with u = m mod 16, fully unrolled). One new k value is
// loaded per m-step from SKEWED smem (a(i)=i+(i>>3): lane addresses 9*t mod 32
// -> conflict-free). x reads are pure broadcasts. FFMA-pipe-bound by design.
// ---------------------------------------------------------------------------
__global__ void __launch_bounds__(NTHREADS)
s4d_conv_kernel(const float* __restrict__ x, float* __restrict__ y)
{
    __shared__ __align__(16) float xs[MT];
    __shared__ __align__(16) float ksm[KSM_SZ];

    int t0 = blockIdx.x * OT;
    int h  = blockIdx.y;
    int b  = blockIdx.z;
    int tid = threadIdx.x;

    const float* xrow = x + (b * H + h) * L;
    const float* krow = g_k + h * L;
    int lcut = g_lcut[h];

    float acc[8];
    #pragma unroll
    for (int j = 0; j < 8; j++) acc[j] = 0.0f;

    int ms = t0 - lcut;
    int m0_start = ms > 0 ? (ms / MT) * MT : 0;
    int s_bt = 8 * tid + MT + 7;     // sidx of this thread's q = b_t (j=0 lag base)

    for (int m0 = m0_start; m0 <= t0; m0 += MT) {
        int qlo = t0 - m0 - MT - 7;  // q stored at sidx = q - qlo
        __syncthreads();
        #pragma unroll
        for (int i = tid; i < MT; i += NTHREADS) xs[i] = xrow[m0 + i];
        #pragma unroll
        for (int i = tid; i < KTOT; i += NTHREADS) {
            int q = qlo + i;
            ksm[i + (i >> 3)] = (q >= 0 && q < L) ? krow[q] : 0.0f;
        }
        __syncthreads();

        // init 16-entry circular k window: entry (v&15) holds k at lag b_t - v
        float kw[16];
        #pragma unroll
        for (int v = -8; v <= 7; v++) {
            int sidx = s_bt - v;
            kw[v & 15] = ksm[sidx + (sidx >> 3)];
        }
        int sidx0 = s_bt - 8;                 // == 7 (mod 8) by construction
        int ab = sidx0 + (sidx0 >> 3);        // skewed addr; -18 per macro-block

        #pragma unroll 1
        for (int mb = 0; mb < MT / 16; mb++) {
            float xr[16];
            #pragma unroll
            for (int g = 0; g < 4; g++) {
                float4 xv = *(const float4*)&xs[16 * mb + 4 * g];
                xr[4 * g + 0] = xv.x; xr[4 * g + 1] = xv.y;
                xr[4 * g + 2] = xv.z; xr[4 * g + 3] = xv.w;
            }
            #pragma unroll
            for (int u = 0; u < 16; u++) {
                float xu = xr[u];
                #pragma unroll
                for (int j = 0; j < 8; j++)
                    acc[j] = fmaf(kw[(u - j) & 15], xu, acc[j]);
                // refill: load lag value for 8 steps ahead
                kw[(u + 8) & 15] = ksm[ab - u - (u >= 8 ? 1 : 0)];
            }
            ab -= 18;
        }
    }

    float* yrow = y + (b * H + h) * L + t0 + 8 * tid;
    float r[8];
    #pragma unroll
    for (int j = 0; j < 8; j++) r[j] = acc[j] > 0.0f ? acc[j] : 0.0f;
    *(float4*)(yrow)     = make_float4(r[0], r[1], r[2], r[3]);
    *(float4*)(yrow + 4) = make_float4(r[4], r[5], r[6], r[7]);
}

// ---------------------------------------------------------------------------
extern "C" void kernel_launch(void* const* d_in, const int* in_sizes, int n_in,
                              void* d_out, int out_size)
{
    const float* x      = (const float*)d_in[0];   // (B, H, L)
    const float* A_real = (const float*)d_in[1];   // (H, N)
    const float* A_imag = (const float*)d_in[2];   // (H, N)
    const float* Bm     = (const float*)d_in[3];   // (1, H, N, 2)
    const float* Cm     = (const float*)d_in[4];   // (1, H, N, 2)
    const float* inv_dt = (const float*)d_in[5];   // (H, 1)
    float* y = (float*)d_out;                      // (B, 1, H, L)

    s4d_params_kernel<<<(H * N_STATE + 255) / 256, 256>>>(A_real, A_imag, Bm, Cm, inv_dt);
    s4d_kgen_kernel<<<dim3(L / 256, H), 256>>>();
    s4d_conv_kernel<<<dim3(L / OT, H, BATCH), NTHREADS>>>(x, y);
}